// round 1
// baseline (speedup 1.0000x reference)
#include <cuda_runtime.h>
#include <math.h>

// Problem constants (fixed by setup_inputs)
#define S_LEN 4096
#define NH 16
#define DK 128
#define DV 128
#define CC 64
#define NCHUNK (S_LEN / CC)
#define SPLIT 4
#define DVS (DV / SPLIT)   // 32
#define NT 256

// smem row strides (floats), padded
#define QS 132
#define KSR 132
#define KTS 68
#define AS 68
#define VS 36
#define STS 36

struct SmemT {
    float q[CC * QS];     // normalized q * Dk^-0.5
    float k[CC * KSR];    // normalized k
    float kt[DK * KTS];   // k transposed
    float A[CC * AS];     // A matrix, then attn matrix
    float v[CC * VS];     // v*beta -> rhs -> v_new
    float st[DK * STS];   // recurrent state slice
    float g[CC];          // cumsum of g
    float egc[CC];        // exp(gc)
    float iegc[CC];       // 1/exp(gc)
    float beta[CC];
    float kdec[CC];       // exp(g_last - gc)
    float kw[CC];         // beta * exp(gc)
};

// C[i0..i0+3][j0..j0+3] += X[i0..][:] @ KT[:][j0..]  (K = DK)
__device__ __forceinline__ void gram_acc(const float* __restrict__ X, int xs,
                                         const float* __restrict__ KT,
                                         int i0, int j0, float acc[4][4]) {
    for (int kk = 0; kk < DK; kk += 4) {
        float av[4][4], bv[4][4];
#pragma unroll
        for (int r = 0; r < 4; ++r) {
            float4 t = *reinterpret_cast<const float4*>(&X[(i0 + r) * xs + kk]);
            av[r][0] = t.x; av[r][1] = t.y; av[r][2] = t.z; av[r][3] = t.w;
        }
#pragma unroll
        for (int u = 0; u < 4; ++u) {
            float4 t = *reinterpret_cast<const float4*>(&KT[(kk + u) * KTS + j0]);
            bv[u][0] = t.x; bv[u][1] = t.y; bv[u][2] = t.z; bv[u][3] = t.w;
        }
#pragma unroll
        for (int r = 0; r < 4; ++r)
#pragma unroll
            for (int c = 0; c < 4; ++c)
                acc[r][c] += av[r][0] * bv[0][c] + av[r][1] * bv[1][c] +
                             av[r][2] * bv[2][c] + av[r][3] * bv[3][c];
    }
}

__global__ __launch_bounds__(NT, 1)
void gdn_kernel(const float* __restrict__ gq, const float* __restrict__ gk,
                const float* __restrict__ gv, const float* __restrict__ gg,
                const float* __restrict__ gb, float* __restrict__ gout) {
    extern __shared__ char smem_raw[];
    SmemT& sm = *reinterpret_cast<SmemT*>(smem_raw);
    const int tid = threadIdx.x;
    const int bh = blockIdx.x / SPLIT;
    const int split = blockIdx.x % SPLIT;
    const int b = bh / NH, h = bh % NH;
    const int warp = tid >> 5, lane = tid & 31;

    // Triangular tile maps for the 64x64 Grams (16x16 grid of 4x4 tiles).
    // 136 lower-incl tiles computed; the other 120 threads zero the strict-upper
    // tiles of the attn matrix.
    int ti = 0, tj = 0, zi = 0, zj = 0;
    const bool isLower = (tid < 136);
    if (isLower) {
        int a = 0;
        while ((a + 1) * (a + 2) / 2 <= tid) ++a;
        ti = a; tj = tid - a * (a + 1) / 2;
    } else {
        int p2 = tid - 136;
        int a = 1;
        while (a * (a + 1) / 2 <= p2) ++a;
        zj = a; zi = p2 - a * (a - 1) / 2;   // zi < zj
    }

    // zero state
    for (int idx = tid; idx < DK * DVS; idx += NT)
        sm.st[(idx / DVS) * STS + (idx % DVS)] = 0.f;

    const float QSCALE = 0.08838834764831845f;  // 128^-0.5
    const int cj = tid & 7;       // c-tile 0..7
    const int c0 = cj * 4;
    const int rg = tid >> 3;      // 0..31

    for (int n = 0; n < NCHUNK; ++n) {
        __syncthreads();   // protects smem reuse across chunks (incl. state init)
        const int s0 = n * CC;

        // ---- phase A: load g/beta; load + l2norm q,k (and build k^T) ----
        if (tid < CC) {
            size_t gidx = ((size_t)b * S_LEN + s0 + tid) * NH + h;
            sm.g[tid] = gg[gidx];
            sm.beta[tid] = gb[gidx];
        }
        for (int r = warp; r < CC; r += 8) {
            size_t rowb = (((size_t)b * S_LEN + s0 + r) * NH + h) * (size_t)DK;
            float4 qv = *reinterpret_cast<const float4*>(gq + rowb + lane * 4);
            float4 kv = *reinterpret_cast<const float4*>(gk + rowb + lane * 4);
            float sq = qv.x * qv.x + qv.y * qv.y + qv.z * qv.z + qv.w * qv.w;
            float sk = kv.x * kv.x + kv.y * kv.y + kv.z * kv.z + kv.w * kv.w;
#pragma unroll
            for (int o = 16; o > 0; o >>= 1) {
                sq += __shfl_xor_sync(0xffffffffu, sq, o);
                sk += __shfl_xor_sync(0xffffffffu, sk, o);
            }
            float rq = rsqrtf(sq + 1e-6f) * QSCALE;
            float rk = rsqrtf(sk + 1e-6f);
            float4 qo = make_float4(qv.x * rq, qv.y * rq, qv.z * rq, qv.w * rq);
            float4 ko = make_float4(kv.x * rk, kv.y * rk, kv.z * rk, kv.w * rk);
            *reinterpret_cast<float4*>(&sm.q[r * QS + lane * 4]) = qo;
            *reinterpret_cast<float4*>(&sm.k[r * KSR + lane * 4]) = ko;
            sm.kt[(lane * 4 + 0) * KTS + r] = ko.x;
            sm.kt[(lane * 4 + 1) * KTS + r] = ko.y;
            sm.kt[(lane * 4 + 2) * KTS + r] = ko.z;
            sm.kt[(lane * 4 + 3) * KTS + r] = ko.w;
        }
        __syncthreads();

        // ---- inclusive scan of g (Hillis-Steele in smem) ----
#pragma unroll
        for (int off = 1; off < CC; off <<= 1) {
            float t = 0.f;
            if (tid < CC && tid >= off) t = sm.g[tid - off];
            __syncthreads();
            if (tid < CC) sm.g[tid] += t;
            __syncthreads();
        }

        // ---- phase C: per-row scalars + v*beta load ----
        if (tid < CC) {
            float gc = sm.g[tid];
            float e = expf(gc);
            sm.egc[tid] = e;
            sm.iegc[tid] = 1.0f / e;
            sm.kdec[tid] = expf(sm.g[CC - 1] - gc);
            sm.kw[tid] = sm.beta[tid] * e;
        }
        for (int idx = tid; idx < CC * (DVS / 4); idx += NT) {
            int r = idx / (DVS / 4);
            int cq = idx % (DVS / 4);
            size_t rowb = (((size_t)b * S_LEN + s0 + r) * NH + h) * (size_t)DV;
            float4 t = *reinterpret_cast<const float4*>(gv + rowb + split * DVS + cq * 4);
            float bt = sm.beta[r];
            t.x *= bt; t.y *= bt; t.z *= bt; t.w *= bt;
            *reinterpret_cast<float4*>(&sm.v[r * VS + cq * 4]) = t;
        }
        __syncthreads();

        // ---- Gram(K,K) -> A (strict lower, scaled) ; plus rhs -= kw*(K@state) ----
        if (isLower) {
            float acc[4][4] = {};
            gram_acc(sm.k, KSR, sm.kt, ti * 4, tj * 4, acc);
#pragma unroll
            for (int r = 0; r < 4; ++r) {
                int i = ti * 4 + r;
                float bi = -sm.beta[i] * sm.egc[i];
                float4 o;
                o.x = (i > tj * 4 + 0) ? bi * sm.iegc[tj * 4 + 0] * acc[r][0] : 0.f;
                o.y = (i > tj * 4 + 1) ? bi * sm.iegc[tj * 4 + 1] * acc[r][1] : 0.f;
                o.z = (i > tj * 4 + 2) ? bi * sm.iegc[tj * 4 + 2] * acc[r][2] : 0.f;
                o.w = (i > tj * 4 + 3) ? bi * sm.iegc[tj * 4 + 3] * acc[r][3] : 0.f;
                *reinterpret_cast<float4*>(&sm.A[i * AS + tj * 4]) = o;
            }
        }
        if (n > 0) {
            const int i0 = rg * 2;
            float acc0[4] = {0, 0, 0, 0}, acc1[4] = {0, 0, 0, 0};
            for (int kk = 0; kk < DK; kk += 4) {
                float4 a0 = *reinterpret_cast<const float4*>(&sm.k[i0 * KSR + kk]);
                float4 a1 = *reinterpret_cast<const float4*>(&sm.k[(i0 + 1) * KSR + kk]);
                float a0a[4] = {a0.x, a0.y, a0.z, a0.w};
                float a1a[4] = {a1.x, a1.y, a1.z, a1.w};
#pragma unroll
                for (int u = 0; u < 4; ++u) {
                    float4 bb = *reinterpret_cast<const float4*>(&sm.st[(kk + u) * STS + c0]);
                    acc0[0] += a0a[u] * bb.x; acc0[1] += a0a[u] * bb.y;
                    acc0[2] += a0a[u] * bb.z; acc0[3] += a0a[u] * bb.w;
                    acc1[0] += a1a[u] * bb.x; acc1[1] += a1a[u] * bb.y;
                    acc1[2] += a1a[u] * bb.z; acc1[3] += a1a[u] * bb.w;
                }
            }
            float kw0 = sm.kw[i0], kw1 = sm.kw[i0 + 1];
            float4 v0 = *reinterpret_cast<float4*>(&sm.v[i0 * VS + c0]);
            float4 v1 = *reinterpret_cast<float4*>(&sm.v[(i0 + 1) * VS + c0]);
            v0.x -= kw0 * acc0[0]; v0.y -= kw0 * acc0[1];
            v0.z -= kw0 * acc0[2]; v0.w -= kw0 * acc0[3];
            v1.x -= kw1 * acc1[0]; v1.y -= kw1 * acc1[1];
            v1.z -= kw1 * acc1[2]; v1.w -= kw1 * acc1[3];
            *reinterpret_cast<float4*>(&sm.v[i0 * VS + c0]) = v0;
            *reinterpret_cast<float4*>(&sm.v[(i0 + 1) * VS + c0]) = v1;
        }
        __syncthreads();

        // ---- forward substitution: (I - A) v_new = rhs, blocked 16 rows ----
        for (int blk = 0; blk < 4; ++blk) {
            const int r0 = blk * 16;
            if (blk > 0) {
                int c = tid & 31;
                int irow = r0 + ((tid >> 5) << 1);
                float a0 = 0.f, a1 = 0.f;
                for (int j = 0; j < r0; ++j) {
                    float vv = sm.v[j * VS + c];
                    a0 += sm.A[irow * AS + j] * vv;
                    a1 += sm.A[(irow + 1) * AS + j] * vv;
                }
                sm.v[irow * VS + c] += a0;
                sm.v[(irow + 1) * VS + c] += a1;
            }
            __syncthreads();
            if (tid < 32) {
                float x[16];
#pragma unroll
                for (int r = 0; r < 16; ++r) {
                    float acc = sm.v[(r0 + r) * VS + tid];
#pragma unroll
                    for (int j = 0; j < 16; ++j)
                        if (j < r) acc += sm.A[(r0 + r) * AS + r0 + j] * x[j];
                    x[r] = acc;
                }
#pragma unroll
                for (int r = 0; r < 16; ++r) sm.v[(r0 + r) * VS + tid] = x[r];
            }
            __syncthreads();
        }

        // ---- Gram(Q,K) -> attn (tril incl, decayed), reuse sm.A ----
        if (isLower) {
            float acc[4][4] = {};
            gram_acc(sm.q, QS, sm.kt, ti * 4, tj * 4, acc);
#pragma unroll
            for (int r = 0; r < 4; ++r) {
                int i = ti * 4 + r;
                float ei = sm.egc[i];
                float4 o;
                o.x = (i >= tj * 4 + 0) ? ei * sm.iegc[tj * 4 + 0] * acc[r][0] : 0.f;
                o.y = (i >= tj * 4 + 1) ? ei * sm.iegc[tj * 4 + 1] * acc[r][1] : 0.f;
                o.z = (i >= tj * 4 + 2) ? ei * sm.iegc[tj * 4 + 2] * acc[r][2] : 0.f;
                o.w = (i >= tj * 4 + 3) ? ei * sm.iegc[tj * 4 + 3] * acc[r][3] : 0.f;
                *reinterpret_cast<float4*>(&sm.A[i * AS + tj * 4]) = o;
            }
        } else {
#pragma unroll
            for (int r = 0; r < 4; ++r)
                *reinterpret_cast<float4*>(&sm.A[(zi * 4 + r) * AS + zj * 4]) =
                    make_float4(0.f, 0.f, 0.f, 0.f);
        }
        __syncthreads();

        // ---- out = (q*egc)@state + attn@v_new, write to gmem ----
        {
            const int i0 = rg * 2;
            float acc0[4] = {0, 0, 0, 0}, acc1[4] = {0, 0, 0, 0};
            for (int kk = 0; kk < DK; kk += 4) {
                float4 a0 = *reinterpret_cast<const float4*>(&sm.q[i0 * QS + kk]);
                float4 a1 = *reinterpret_cast<const float4*>(&sm.q[(i0 + 1) * QS + kk]);
                float a0a[4] = {a0.x, a0.y, a0.z, a0.w};
                float a1a[4] = {a1.x, a1.y, a1.z, a1.w};
#pragma unroll
                for (int u = 0; u < 4; ++u) {
                    float4 bb = *reinterpret_cast<const float4*>(&sm.st[(kk + u) * STS + c0]);
                    acc0[0] += a0a[u] * bb.x; acc0[1] += a0a[u] * bb.y;
                    acc0[2] += a0a[u] * bb.z; acc0[3] += a0a[u] * bb.w;
                    acc1[0] += a1a[u] * bb.x; acc1[1] += a1a[u] * bb.y;
                    acc1[2] += a1a[u] * bb.z; acc1[3] += a1a[u] * bb.w;
                }
            }
            float e0 = sm.egc[i0], e1 = sm.egc[i0 + 1];
#pragma unroll
            for (int c = 0; c < 4; ++c) { acc0[c] *= e0; acc1[c] *= e1; }
            for (int j = 0; j < CC; j += 4) {
                float4 a0 = *reinterpret_cast<const float4*>(&sm.A[i0 * AS + j]);
                float4 a1 = *reinterpret_cast<const float4*>(&sm.A[(i0 + 1) * AS + j]);
                float a0a[4] = {a0.x, a0.y, a0.z, a0.w};
                float a1a[4] = {a1.x, a1.y, a1.z, a1.w};
#pragma unroll
                for (int u = 0; u < 4; ++u) {
                    float4 bb = *reinterpret_cast<const float4*>(&sm.v[(j + u) * VS + c0]);
                    acc0[0] += a0a[u] * bb.x; acc0[1] += a0a[u] * bb.y;
                    acc0[2] += a0a[u] * bb.z; acc0[3] += a0a[u] * bb.w;
                    acc1[0] += a1a[u] * bb.x; acc1[1] += a1a[u] * bb.y;
                    acc1[2] += a1a[u] * bb.z; acc1[3] += a1a[u] * bb.w;
                }
            }
            size_t ob0 = (((size_t)b * S_LEN + s0 + i0) * NH + h) * (size_t)DV +
                         split * DVS + c0;
            *reinterpret_cast<float4*>(gout + ob0) =
                make_float4(acc0[0], acc0[1], acc0[2], acc0[3]);
            *reinterpret_cast<float4*>(gout + ob0 + (size_t)NH * DV) =
                make_float4(acc1[0], acc1[1], acc1[2], acc1[3]);
        }
        __syncthreads();

        // ---- state = state*exp(g_last) + (k*exp(g_last-gc))^T @ v_new ----
        {
            const int k0 = rg * 4;
            float acc[4][4] = {{0}};
            for (int i = 0; i < CC; ++i) {
                float kd = sm.kdec[i];
                float4 ak = *reinterpret_cast<const float4*>(&sm.k[i * KSR + k0]);
                float4 bv = *reinterpret_cast<const float4*>(&sm.v[i * VS + c0]);
                float b0 = kd * bv.x, b1 = kd * bv.y, b2 = kd * bv.z, b3 = kd * bv.w;
                acc[0][0] += ak.x * b0; acc[0][1] += ak.x * b1;
                acc[0][2] += ak.x * b2; acc[0][3] += ak.x * b3;
                acc[1][0] += ak.y * b0; acc[1][1] += ak.y * b1;
                acc[1][2] += ak.y * b2; acc[1][3] += ak.y * b3;
                acc[2][0] += ak.z * b0; acc[2][1] += ak.z * b1;
                acc[2][2] += ak.z * b2; acc[2][3] += ak.z * b3;
                acc[3][0] += ak.w * b0; acc[3][1] += ak.w * b1;
                acc[3][2] += ak.w * b2; acc[3][3] += ak.w * b3;
            }
            float egl = sm.egc[CC - 1];
#pragma unroll
            for (int u = 0; u < 4; ++u) {
                float4 s = *reinterpret_cast<float4*>(&sm.st[(k0 + u) * STS + c0]);
                s.x = s.x * egl + acc[u][0];
                s.y = s.y * egl + acc[u][1];
                s.z = s.z * egl + acc[u][2];
                s.w = s.w * egl + acc[u][3];
                *reinterpret_cast<float4*>(&sm.st[(k0 + u) * STS + c0]) = s;
            }
        }
    }
}

extern "C" void kernel_launch(void* const* d_in, const int* in_sizes, int n_in,
                              void* d_out, int out_size) {
    const float* q = (const float*)d_in[0];
    const float* k = (const float*)d_in[1];
    const float* v = (const float*)d_in[2];
    const float* g = (const float*)d_in[3];
    const float* beta = (const float*)d_in[4];
    float* out = (float*)d_out;

    int B = in_sizes[0] / (S_LEN * NH * DK);
    if (B < 1) B = 1;

    cudaFuncSetAttribute(gdn_kernel, cudaFuncAttributeMaxDynamicSharedMemorySize,
                         (int)sizeof(SmemT));
    gdn_kernel<<<B * NH * SPLIT, NT, sizeof(SmemT)>>>(q, k, v, g, beta, out);
}

// round 3
// speedup vs baseline: 1.7096x; 1.7096x over previous
#include <cuda_runtime.h>
#include <cuda_bf16.h>
#include <math.h>

// Problem constants (fixed by setup_inputs)
#define S_LEN 4096
#define NH 16
#define DK 128
#define DV 128
#define CC 64
#define NCHUNK (S_LEN / CC)
#define SPLIT 4
#define DVS (DV / SPLIT)   // 32
#define NT 256

// smem strides (elements)
#define KHS 136   // bf16 stride: khi/klo/qhi/qlo (64 rows x 128) and shi/slo (32 x 128)
#define STS 132   // fp32 stride: state^T (32 x 128)
#define AS  68    // fp32 stride: A (64 x 64)
#define ATS 72    // bf16 stride: attn' (64 x 64)
#define VS  36    // fp32 stride: v / rhs / v_new (64 x 32)
#define VTS 72    // bf16 stride: v_new^T * kdec (32 x 64)

struct __align__(16) SmemT {
    float st[32 * STS];                       // state^T fp32 [dv][dk]
    float A[CC * AS];                         // WY matrix (fp32, for solve)
    float v[CC * VS];                         // v*beta -> rhs -> v_new
    __nv_bfloat16 khi[CC * KHS], klo[CC * KHS];
    __nv_bfloat16 qhi[CC * KHS], qlo[CC * KHS];   // q * Dk^-.5 * e^{gc}
    __nv_bfloat16 shi[32 * KHS], slo[32 * KHS];   // state^T hi/lo
    __nv_bfloat16 athi[CC * ATS], atlo[CC * ATS]; // attn' = (Qg@K^T)*e^{-glast}, masked
    __nv_bfloat16 vthi[32 * VTS], vtlo[32 * VTS]; // (v_new * kdec)^T
    float g[CC], egc[CC], iegc[CC], beta[CC], kdec[CC], kw[CC];
};

__device__ __forceinline__ void bsplit(float x, __nv_bfloat16& hi, __nv_bfloat16& lo) {
    hi = __float2bfloat16(x);
    lo = __float2bfloat16(x - __bfloat162float(hi));
}

__device__ __forceinline__ void mma16816(float* d, unsigned a0, unsigned a1,
                                         unsigned a2, unsigned a3,
                                         unsigned b0, unsigned b1) {
    asm volatile(
        "mma.sync.aligned.m16n8k16.row.col.f32.bf16.bf16.f32 "
        "{%0,%1,%2,%3}, {%4,%5,%6,%7}, {%8,%9}, {%0,%1,%2,%3};\n"
        : "+f"(d[0]), "+f"(d[1]), "+f"(d[2]), "+f"(d[3])
        : "r"(a0), "r"(a1), "r"(a2), "r"(a3), "r"(b0), "r"(b1));
}

// A fragment (16x16), row-major source with k contiguous
__device__ __forceinline__ void ldA(const __nv_bfloat16* p, int stride, int row0,
                                    int k0, int gq, int tig, unsigned* a) {
    int c = k0 + 2 * tig;
    a[0] = *reinterpret_cast<const unsigned*>(p + (row0 + gq) * stride + c);
    a[1] = *reinterpret_cast<const unsigned*>(p + (row0 + gq + 8) * stride + c);
    a[2] = *reinterpret_cast<const unsigned*>(p + (row0 + gq) * stride + c + 8);
    a[3] = *reinterpret_cast<const unsigned*>(p + (row0 + gq + 8) * stride + c + 8);
}

// B fragment (16x8) from matrix stored [n][k] with k contiguous (B[k][n] = M[n][k])
__device__ __forceinline__ void ldB(const __nv_bfloat16* p, int stride, int n0,
                                    int k0, int gq, int tig, unsigned* bb) {
    int c = k0 + 2 * tig;
    bb[0] = *reinterpret_cast<const unsigned*>(p + (n0 + gq) * stride + c);
    bb[1] = *reinterpret_cast<const unsigned*>(p + (n0 + gq) * stride + c + 8);
}

// B fragment from matrix stored [k][n] with n contiguous (transposed gather)
__device__ __forceinline__ void ldBtrans(const __nv_bfloat16* p, int stride, int n,
                                         int k0, int tig, unsigned* bb) {
    const unsigned short* s = reinterpret_cast<const unsigned short*>(p);
    int r = k0 + 2 * tig;
    unsigned l0 = s[r * stride + n], h0 = s[(r + 1) * stride + n];
    unsigned l1 = s[(r + 8) * stride + n], h1 = s[(r + 9) * stride + n];
    bb[0] = l0 | (h0 << 16);
    bb[1] = l1 | (h1 << 16);
}

__global__ __launch_bounds__(NT, 1)
void gdn_kernel(const float* __restrict__ gq, const float* __restrict__ gk,
                const float* __restrict__ gv, const float* __restrict__ gg,
                const float* __restrict__ gb, float* __restrict__ gout) {
    extern __shared__ char smem_raw[];
    SmemT& sm = *reinterpret_cast<SmemT*>(smem_raw);
    const int tid = threadIdx.x;
    const int bh = blockIdx.x / SPLIT;
    const int split = blockIdx.x % SPLIT;
    const int b = bh / NH, h = bh % NH;
    const int warp = tid >> 5, lane = tid & 31;
    const int gq_ = lane >> 2, tig = lane & 3;

    // zero recurrent state (fp32 + bf16 halves)
    for (int i = tid; i < 32 * STS; i += NT) sm.st[i] = 0.f;
    const __nv_bfloat16 bz = __float2bfloat16(0.f);
    for (int i = tid; i < 32 * KHS; i += NT) { sm.shi[i] = bz; sm.slo[i] = bz; }

    const float QSCALE = 0.08838834764831845f;  // 128^-0.5

    for (int n = 0; n < NCHUNK; ++n) {
        __syncthreads();   // state/smem reuse barrier between chunks
        const int s0 = n * CC;

        // ---- P0a: g/beta, inclusive scan, per-row scalars ----
        if (tid < CC) {
            size_t gidx = ((size_t)b * S_LEN + s0 + tid) * NH + h;
            sm.g[tid] = gg[gidx];
            sm.beta[tid] = gb[gidx];
        }
        __syncthreads();
#pragma unroll
        for (int off = 1; off < CC; off <<= 1) {
            float t = 0.f;
            if (tid < CC && tid >= off) t = sm.g[tid - off];
            __syncthreads();
            if (tid < CC) sm.g[tid] += t;
            __syncthreads();
        }
        if (tid < CC) {
            float gc = sm.g[tid];
            sm.egc[tid] = expf(gc);
            sm.iegc[tid] = expf(-gc);
            sm.kdec[tid] = expf(sm.g[CC - 1] - gc);
            sm.kw[tid] = sm.beta[tid] * expf(gc);
        }
        __syncthreads();

        // ---- P0b: load+normalize k and q (q scaled by e^{gc}), split; load v*beta ----
        for (int r = warp; r < CC; r += 8) {
            size_t rowb = (((size_t)b * S_LEN + s0 + r) * NH + h) * (size_t)DK;
            float4 qv = *reinterpret_cast<const float4*>(gq + rowb + lane * 4);
            float4 kv = *reinterpret_cast<const float4*>(gk + rowb + lane * 4);
            float sq = qv.x * qv.x + qv.y * qv.y + qv.z * qv.z + qv.w * qv.w;
            float sk = kv.x * kv.x + kv.y * kv.y + kv.z * kv.z + kv.w * kv.w;
#pragma unroll
            for (int o = 16; o > 0; o >>= 1) {
                sq += __shfl_xor_sync(0xffffffffu, sq, o);
                sk += __shfl_xor_sync(0xffffffffu, sk, o);
            }
            float rq = rsqrtf(sq + 1e-6f) * QSCALE * sm.egc[r];
            float rk = rsqrtf(sk + 1e-6f);
            float qa[4] = {qv.x * rq, qv.y * rq, qv.z * rq, qv.w * rq};
            float ka[4] = {kv.x * rk, kv.y * rk, kv.z * rk, kv.w * rk};
#pragma unroll
            for (int t = 0; t < 4; ++t) {
                __nv_bfloat16 hi, lo;
                bsplit(ka[t], hi, lo);
                sm.khi[r * KHS + lane * 4 + t] = hi;
                sm.klo[r * KHS + lane * 4 + t] = lo;
                bsplit(qa[t], hi, lo);
                sm.qhi[r * KHS + lane * 4 + t] = hi;
                sm.qlo[r * KHS + lane * 4 + t] = lo;
            }
        }
        for (int idx = tid; idx < CC * (DVS / 4); idx += NT) {
            int r = idx / (DVS / 4);
            int cq = idx % (DVS / 4);
            size_t rowb = (((size_t)b * S_LEN + s0 + r) * NH + h) * (size_t)DV;
            float4 t = *reinterpret_cast<const float4*>(gv + rowb + split * DVS + cq * 4);
            float bt = sm.beta[r];
            t.x *= bt; t.y *= bt; t.z *= bt; t.w *= bt;
            *reinterpret_cast<float4*>(&sm.v[r * VS + cq * 4]) = t;
        }
        __syncthreads();

        // ---- P1: Grams  G=K@K^T and QK=Qg@K^T  (16x32 warp tiles, 4x2 grid) ----
        {
            const int m0 = (warp >> 1) * 16, n0 = (warp & 1) * 32;
            float accG[4][4], accQ[4][4];
#pragma unroll
            for (int t = 0; t < 4; ++t)
#pragma unroll
                for (int e = 0; e < 4; ++e) { accG[t][e] = 0.f; accQ[t][e] = 0.f; }
            if (m0 + 15 >= n0) {   // skip fully-upper tiles
                for (int k0 = 0; k0 < DK; k0 += 16) {
                    unsigned kh[4], kl[4], qh[4], ql[4];
                    ldA(sm.khi, KHS, m0, k0, gq_, tig, kh);
                    ldA(sm.klo, KHS, m0, k0, gq_, tig, kl);
                    ldA(sm.qhi, KHS, m0, k0, gq_, tig, qh);
                    ldA(sm.qlo, KHS, m0, k0, gq_, tig, ql);
#pragma unroll
                    for (int nt = 0; nt < 4; ++nt) {
                        unsigned bhh[2], bll[2];
                        ldB(sm.khi, KHS, n0 + nt * 8, k0, gq_, tig, bhh);
                        ldB(sm.klo, KHS, n0 + nt * 8, k0, gq_, tig, bll);
                        mma16816(accG[nt], kh[0], kh[1], kh[2], kh[3], bhh[0], bhh[1]);
                        mma16816(accG[nt], kh[0], kh[1], kh[2], kh[3], bll[0], bll[1]);
                        mma16816(accG[nt], kl[0], kl[1], kl[2], kl[3], bhh[0], bhh[1]);
                        mma16816(accQ[nt], qh[0], qh[1], qh[2], qh[3], bhh[0], bhh[1]);
                        mma16816(accQ[nt], qh[0], qh[1], qh[2], qh[3], bll[0], bll[1]);
                        mma16816(accQ[nt], ql[0], ql[1], ql[2], ql[3], bhh[0], bhh[1]);
                    }
                }
            }
            float einv = sm.iegc[CC - 1];   // e^{-g_last}
#pragma unroll
            for (int nt = 0; nt < 4; ++nt)
#pragma unroll
                for (int e = 0; e < 4; ++e) {
                    int i = m0 + gq_ + ((e >> 1) << 3);
                    int j = n0 + nt * 8 + 2 * tig + (e & 1);
                    float Av = (i > j) ? -sm.beta[i] * sm.egc[i] * sm.iegc[j] * accG[nt][e]
                                       : 0.f;
                    sm.A[i * AS + j] = Av;
                    float atv = (i >= j) ? accQ[nt][e] * einv : 0.f;
                    __nv_bfloat16 hi, lo; bsplit(atv, hi, lo);
                    sm.athi[i * ATS + j] = hi;
                    sm.atlo[i * ATS + j] = lo;
                }
        }

        // ---- P2: rhs^T = State^T @ K^T; v[c][dv] -= kw_c * P  (16x16 tiles, 2x4) ----
        {
            const int m0 = (warp & 1) * 16, n0 = (warp >> 1) * 16;
            float acc[2][4];
#pragma unroll
            for (int t = 0; t < 2; ++t)
#pragma unroll
                for (int e = 0; e < 4; ++e) acc[t][e] = 0.f;
            for (int k0 = 0; k0 < DK; k0 += 16) {
                unsigned ah[4], al[4];
                ldA(sm.shi, KHS, m0, k0, gq_, tig, ah);
                ldA(sm.slo, KHS, m0, k0, gq_, tig, al);
#pragma unroll
                for (int nt = 0; nt < 2; ++nt) {
                    unsigned bhh[2], bll[2];
                    ldB(sm.khi, KHS, n0 + nt * 8, k0, gq_, tig, bhh);
                    ldB(sm.klo, KHS, n0 + nt * 8, k0, gq_, tig, bll);
                    mma16816(acc[nt], ah[0], ah[1], ah[2], ah[3], bhh[0], bhh[1]);
                    mma16816(acc[nt], ah[0], ah[1], ah[2], ah[3], bll[0], bll[1]);
                    mma16816(acc[nt], al[0], al[1], al[2], al[3], bhh[0], bhh[1]);
                }
            }
#pragma unroll
            for (int nt = 0; nt < 2; ++nt)
#pragma unroll
                for (int e = 0; e < 4; ++e) {
                    int i = m0 + gq_ + ((e >> 1) << 3);             // dv
                    int j = n0 + nt * 8 + 2 * tig + (e & 1);        // c
                    sm.v[j * VS + i] -= sm.kw[j] * acc[nt][e];
                }
        }
        __syncthreads();

        // ---- P3: forward substitution (I - A) v_new = rhs, blocked 16 rows ----
        for (int blk = 0; blk < 4; ++blk) {
            const int r0 = blk * 16;
            if (blk > 0) {
                int c = tid & 31;
                int irow = r0 + ((tid >> 5) << 1);
                float a0 = 0.f, a1 = 0.f;
                for (int j = 0; j < r0; ++j) {
                    float vv = sm.v[j * VS + c];
                    a0 += sm.A[irow * AS + j] * vv;
                    a1 += sm.A[(irow + 1) * AS + j] * vv;
                }
                sm.v[irow * VS + c] += a0;
                sm.v[(irow + 1) * VS + c] += a1;
            }
            __syncthreads();
            if (tid < 32) {
                float x[16];
#pragma unroll
                for (int r = 0; r < 16; ++r) {
                    float acc = sm.v[(r0 + r) * VS + tid];
#pragma unroll
                    for (int j = 0; j < 16; ++j)
                        if (j < r) acc += sm.A[(r0 + r) * AS + r0 + j] * x[j];
                    x[r] = acc;
                }
#pragma unroll
                for (int r = 0; r < 16; ++r) sm.v[(r0 + r) * VS + tid] = x[r];
            }
            __syncthreads();
        }

        // ---- split (v_new * kdec)^T into bf16 hi/lo ----
        for (int idx = tid; idx < CC * DVS; idx += NT) {
            int c = idx >> 5, m = idx & 31;
            float x = sm.v[c * VS + m] * sm.kdec[c];
            __nv_bfloat16 hi, lo; bsplit(x, hi, lo);
            sm.vthi[m * VTS + c] = hi;
            sm.vtlo[m * VTS + c] = lo;
        }
        __syncthreads();

        // ---- P4: out^T = State^T@Qg^T + Vnewd^T@attn'^T  (16x16 tiles, 2x4) ----
        {
            const int m0 = (warp & 1) * 16, n0 = (warp >> 1) * 16;
            float acc[2][4];
#pragma unroll
            for (int t = 0; t < 2; ++t)
#pragma unroll
                for (int e = 0; e < 4; ++e) acc[t][e] = 0.f;
            for (int k0 = 0; k0 < DK; k0 += 16) {
                unsigned ah[4], al[4];
                ldA(sm.shi, KHS, m0, k0, gq_, tig, ah);
                ldA(sm.slo, KHS, m0, k0, gq_, tig, al);
#pragma unroll
                for (int nt = 0; nt < 2; ++nt) {
                    unsigned bhh[2], bll[2];
                    ldB(sm.qhi, KHS, n0 + nt * 8, k0, gq_, tig, bhh);
                    ldB(sm.qlo, KHS, n0 + nt * 8, k0, gq_, tig, bll);
                    mma16816(acc[nt], ah[0], ah[1], ah[2], ah[3], bhh[0], bhh[1]);
                    mma16816(acc[nt], ah[0], ah[1], ah[2], ah[3], bll[0], bll[1]);
                    mma16816(acc[nt], al[0], al[1], al[2], al[3], bhh[0], bhh[1]);
                }
            }
            for (int k0 = 0; k0 < CC; k0 += 16) {
                unsigned ah[4], al[4];
                ldA(sm.vthi, VTS, m0, k0, gq_, tig, ah);
                ldA(sm.vtlo, VTS, m0, k0, gq_, tig, al);
#pragma unroll
                for (int nt = 0; nt < 2; ++nt) {
                    unsigned bhh[2], bll[2];
                    ldB(sm.athi, ATS, n0 + nt * 8, k0, gq_, tig, bhh);
                    ldB(sm.atlo, ATS, n0 + nt * 8, k0, gq_, tig, bll);
                    mma16816(acc[nt], ah[0], ah[1], ah[2], ah[3], bhh[0], bhh[1]);
                    mma16816(acc[nt], ah[0], ah[1], ah[2], ah[3], bll[0], bll[1]);
                    mma16816(acc[nt], al[0], al[1], al[2], al[3], bhh[0], bhh[1]);
                }
            }
#pragma unroll
            for (int nt = 0; nt < 2; ++nt)
#pragma unroll
                for (int e = 0; e < 4; ++e) {
                    int dv = m0 + gq_ + ((e >> 1) << 3);
                    int c = n0 + nt * 8 + 2 * tig + (e & 1);
                    size_t ob = (((size_t)b * S_LEN + s0 + c) * NH + h) * (size_t)DV +
                                split * DVS + dv;
                    gout[ob] = acc[nt][e];
                }
        }

        // ---- P5: State^T = e^{glast} State^T + Vnewd^T @ K  (16x32 tiles, 2x4) ----
        {
            const int m0 = (warp & 1) * 16, n0 = (warp >> 1) * 32;
            float acc[4][4];
#pragma unroll
            for (int t = 0; t < 4; ++t)
#pragma unroll
                for (int e = 0; e < 4; ++e) acc[t][e] = 0.f;
            for (int k0 = 0; k0 < CC; k0 += 16) {
                unsigned ah[4], al[4];
                ldA(sm.vthi, VTS, m0, k0, gq_, tig, ah);
                ldA(sm.vtlo, VTS, m0, k0, gq_, tig, al);
#pragma unroll
                for (int nt = 0; nt < 4; ++nt) {
                    int nn = n0 + nt * 8 + gq_;
                    unsigned bhh[2], bll[2];
                    ldBtrans(sm.khi, KHS, nn, k0, tig, bhh);
                    ldBtrans(sm.klo, KHS, nn, k0, tig, bll);
                    mma16816(acc[nt], ah[0], ah[1], ah[2], ah[3], bhh[0], bhh[1]);
                    mma16816(acc[nt], ah[0], ah[1], ah[2], ah[3], bll[0], bll[1]);
                    mma16816(acc[nt], al[0], al[1], al[2], al[3], bhh[0], bhh[1]);
                }
            }
            float egl = sm.egc[CC - 1];
#pragma unroll
            for (int nt = 0; nt < 4; ++nt)
#pragma unroll
                for (int e = 0; e < 4; ++e) {
                    int dv = m0 + gq_ + ((e >> 1) << 3);
                    int dk = n0 + nt * 8 + 2 * tig + (e & 1);
                    float s = sm.st[dv * STS + dk] * egl + acc[nt][e];
                    sm.st[dv * STS + dk] = s;
                    __nv_bfloat16 hi, lo; bsplit(s, hi, lo);
                    sm.shi[dv * KHS + dk] = hi;
                    sm.slo[dv * KHS + dk] = lo;
                }
        }
    }
}

extern "C" void kernel_launch(void* const* d_in, const int* in_sizes, int n_in,
                              void* d_out, int out_size) {
    const float* q = (const float*)d_in[0];
    const float* k = (const float*)d_in[1];
    const float* v = (const float*)d_in[2];
    const float* g = (const float*)d_in[3];
    const float* beta = (const float*)d_in[4];
    float* out = (float*)d_out;

    int B = in_sizes[0] / (S_LEN * NH * DK);
    if (B < 1) B = 1;

    cudaFuncSetAttribute(gdn_kernel, cudaFuncAttributeMaxDynamicSharedMemorySize,
                         (int)sizeof(SmemT));
    gdn_kernel<<<B * NH * SPLIT, NT, sizeof(SmemT)>>>(q, k, v, g, beta, out);
}

// round 4
// speedup vs baseline: 2.3158x; 1.3546x over previous
#include <cuda_runtime.h>
#include <cuda_bf16.h>
#include <math.h>

// Problem constants (fixed by setup_inputs)
#define S_LEN 4096
#define NH 16
#define DK 128
#define DV 128
#define CC 64
#define NCHUNK (S_LEN / CC)
#define SPLIT 4
#define DVS (DV / SPLIT)   // 32
#define NT 256

// smem strides (elements)
#define KHS 136   // bf16 stride: khi/klo/qhi/qlo (64 x 128) and shi/slo (32 x 128)
#define AS  68    // fp32 stride: A (64 x 64)
#define ATS 72    // bf16 stride: attn' (64 x 64)
#define VS  36    // fp32 stride: v / rhs / v_new (64 x 32)
#define VTS 72    // bf16 stride: v_new^T * kdec (32 x 64)

struct __align__(16) SmemT {
    float A[CC * AS];                         // WY matrix (fp32, for solve)
    float v[CC * VS];                         // v*beta -> rhs -> v_new
    float Ti[4 * 16 * 17];                    // inverted 16x16 diagonal blocks
    __nv_bfloat16 khi[CC * KHS], klo[CC * KHS];
    __nv_bfloat16 qhi[CC * KHS], qlo[CC * KHS];   // q * Dk^-.5 * e^{gc}
    __nv_bfloat16 shi[32 * KHS], slo[32 * KHS];   // state^T hi/lo
    __nv_bfloat16 athi[CC * ATS], atlo[CC * ATS]; // attn' masked
    __nv_bfloat16 vthi[32 * VTS], vtlo[32 * VTS]; // (v_new * kdec)^T
    float qraw[CC * 128], kraw[CC * 128], vraw[CC * 32];   // cp.async staging
    float gst[CC], bst[CC];                   // staged g, beta
    float egc[CC], iegc[CC], kdec[CC], kw[CC], negbe[CC];
};

__device__ __forceinline__ void bsplit(float x, __nv_bfloat16& hi, __nv_bfloat16& lo) {
    hi = __float2bfloat16(x);
    lo = __float2bfloat16(x - __bfloat162float(hi));
}

__device__ __forceinline__ void mma16816(float* d, unsigned a0, unsigned a1,
                                         unsigned a2, unsigned a3,
                                         unsigned b0, unsigned b1) {
    asm volatile(
        "mma.sync.aligned.m16n8k16.row.col.f32.bf16.bf16.f32 "
        "{%0,%1,%2,%3}, {%4,%5,%6,%7}, {%8,%9}, {%0,%1,%2,%3};\n"
        : "+f"(d[0]), "+f"(d[1]), "+f"(d[2]), "+f"(d[3])
        : "r"(a0), "r"(a1), "r"(a2), "r"(a3), "r"(b0), "r"(b1));
}

__device__ __forceinline__ void ldA(const __nv_bfloat16* p, int stride, int row0,
                                    int k0, int gq, int tig, unsigned* a) {
    int c = k0 + 2 * tig;
    a[0] = *reinterpret_cast<const unsigned*>(p + (row0 + gq) * stride + c);
    a[1] = *reinterpret_cast<const unsigned*>(p + (row0 + gq + 8) * stride + c);
    a[2] = *reinterpret_cast<const unsigned*>(p + (row0 + gq) * stride + c + 8);
    a[3] = *reinterpret_cast<const unsigned*>(p + (row0 + gq + 8) * stride + c + 8);
}

__device__ __forceinline__ void ldB(const __nv_bfloat16* p, int stride, int n0,
                                    int k0, int gq, int tig, unsigned* bb) {
    int c = k0 + 2 * tig;
    bb[0] = *reinterpret_cast<const unsigned*>(p + (n0 + gq) * stride + c);
    bb[1] = *reinterpret_cast<const unsigned*>(p + (n0 + gq) * stride + c + 8);
}

__device__ __forceinline__ void ldBtrans(const __nv_bfloat16* p, int stride, int n,
                                         int k0, int tig, unsigned* bb) {
    const unsigned short* s = reinterpret_cast<const unsigned short*>(p);
    int r = k0 + 2 * tig;
    unsigned l0 = s[r * stride + n], h0 = s[(r + 1) * stride + n];
    unsigned l1 = s[(r + 8) * stride + n], h1 = s[(r + 9) * stride + n];
    bb[0] = l0 | (h0 << 16);
    bb[1] = l1 | (h1 << 16);
}

__device__ __forceinline__ void cpa16(void* dst, const void* src) {
    unsigned d = (unsigned)__cvta_generic_to_shared(dst);
    asm volatile("cp.async.cg.shared.global [%0], [%1], 16;\n" :: "r"(d), "l"(src));
}
__device__ __forceinline__ void cpa4(void* dst, const void* src) {
    unsigned d = (unsigned)__cvta_generic_to_shared(dst);
    asm volatile("cp.async.ca.shared.global [%0], [%1], 4;\n" :: "r"(d), "l"(src));
}

// prefetch chunk m raw data into staging
__device__ __forceinline__ void prefetch_chunk(SmemT& sm, int m, int b, int h,
                                               int split, int tid,
                                               const float* gq, const float* gk,
                                               const float* gv, const float* gg,
                                               const float* gb) {
    for (int i = tid; i < CC * 32; i += NT) {
        int r = i >> 5, cq = i & 31;
        size_t rowb = (((size_t)b * S_LEN + m * CC + r) * NH + h) * (size_t)DK;
        cpa16(&sm.qraw[r * 128 + cq * 4], gq + rowb + cq * 4);
        cpa16(&sm.kraw[r * 128 + cq * 4], gk + rowb + cq * 4);
    }
    for (int i = tid; i < CC * 8; i += NT) {
        int r = i >> 3, cq = i & 7;
        size_t rowb = (((size_t)b * S_LEN + m * CC + r) * NH + h) * (size_t)DV;
        cpa16(&sm.vraw[r * 32 + cq * 4], gv + rowb + split * DVS + cq * 4);
    }
    if (tid < CC) {
        size_t gi = ((size_t)b * S_LEN + m * CC + tid) * NH + h;
        cpa4(&sm.gst[tid], gg + gi);
        cpa4(&sm.bst[tid], gb + gi);
    }
    asm volatile("cp.async.commit_group;\n");
}

__global__ __launch_bounds__(NT, 1)
void gdn_kernel(const float* __restrict__ gq, const float* __restrict__ gk,
                const float* __restrict__ gv, const float* __restrict__ gg,
                const float* __restrict__ gb, float* __restrict__ gout) {
    extern __shared__ char smem_raw[];
    SmemT& sm = *reinterpret_cast<SmemT*>(smem_raw);
    const int tid = threadIdx.x;
    const int bh = blockIdx.x / SPLIT;
    const int split = blockIdx.x % SPLIT;
    const int b = bh / NH, h = bh % NH;
    const int warp = tid >> 5, lane = tid & 31;
    const int gq_ = lane >> 2, tig = lane & 3;

    // zero recurrent state (bf16 halves only; no fp32 master)
    const __nv_bfloat16 bz = __float2bfloat16(0.f);
    for (int i = tid; i < 32 * KHS; i += NT) { sm.shi[i] = bz; sm.slo[i] = bz; }

    // prologue: prefetch chunk 0
    prefetch_chunk(sm, 0, b, h, split, tid, gq, gk, gv, gg, gb);

    const float QSCALE = 0.08838834764831845f;  // 128^-0.5

    for (int n = 0; n < NCHUNK; ++n) {
        const int s0 = n * CC;
        asm volatile("cp.async.wait_group 0;\n");
        __syncthreads();   // staging ready; prev chunk fully done

        // ---- phase A: warp0 scan+scalars; warps 1-7: v*beta ----
        if (warp == 0) {
            float a0 = sm.gst[lane];
            float a1 = sm.gst[lane + 32];
#pragma unroll
            for (int off = 1; off < 32; off <<= 1) {
                float t = __shfl_up_sync(0xffffffffu, a0, off);
                if (lane >= off) a0 += t;
            }
            float tot0 = __shfl_sync(0xffffffffu, a0, 31);
#pragma unroll
            for (int off = 1; off < 32; off <<= 1) {
                float t = __shfl_up_sync(0xffffffffu, a1, off);
                if (lane >= off) a1 += t;
            }
            a1 += tot0;
            float glast = __shfl_sync(0xffffffffu, a1, 31);
            float e0 = expf(a0), e1 = expf(a1);
            sm.egc[lane] = e0;               sm.egc[lane + 32] = e1;
            sm.iegc[lane] = expf(-a0);       sm.iegc[lane + 32] = expf(-a1);
            sm.kdec[lane] = expf(glast - a0); sm.kdec[lane + 32] = expf(glast - a1);
            float b0 = sm.bst[lane], b1 = sm.bst[lane + 32];
            sm.kw[lane] = b0 * e0;           sm.kw[lane + 32] = b1 * e1;
            sm.negbe[lane] = -b0 * e0;       sm.negbe[lane + 32] = -b1 * e1;
        } else {
            for (int i = tid - 32; i < CC * 8; i += NT - 32) {
                int r = i >> 3, cq = i & 7;
                float4 t = *reinterpret_cast<const float4*>(&sm.vraw[r * 32 + cq * 4]);
                float bt = sm.bst[r];
                t.x *= bt; t.y *= bt; t.z *= bt; t.w *= bt;
                *reinterpret_cast<float4*>(&sm.v[r * VS + cq * 4]) = t;
            }
        }
        __syncthreads();

        // ---- phase B: k+q norm/split from staging ----
        for (int r = warp; r < CC; r += 8) {
            float4 qv = *reinterpret_cast<const float4*>(&sm.qraw[r * 128 + lane * 4]);
            float4 kv = *reinterpret_cast<const float4*>(&sm.kraw[r * 128 + lane * 4]);
            float sq = qv.x * qv.x + qv.y * qv.y + qv.z * qv.z + qv.w * qv.w;
            float sk = kv.x * kv.x + kv.y * kv.y + kv.z * kv.z + kv.w * kv.w;
#pragma unroll
            for (int o = 16; o > 0; o >>= 1) {
                sq += __shfl_xor_sync(0xffffffffu, sq, o);
                sk += __shfl_xor_sync(0xffffffffu, sk, o);
            }
            float rq = rsqrtf(sq + 1e-6f) * QSCALE * sm.egc[r];
            float rk = rsqrtf(sk + 1e-6f);
            float qa[4] = {qv.x * rq, qv.y * rq, qv.z * rq, qv.w * rq};
            float ka[4] = {kv.x * rk, kv.y * rk, kv.z * rk, kv.w * rk};
#pragma unroll
            for (int t = 0; t < 4; ++t) {
                __nv_bfloat16 hi, lo;
                bsplit(ka[t], hi, lo);
                sm.khi[r * KHS + lane * 4 + t] = hi;
                sm.klo[r * KHS + lane * 4 + t] = lo;
                bsplit(qa[t], hi, lo);
                sm.qhi[r * KHS + lane * 4 + t] = hi;
                sm.qlo[r * KHS + lane * 4 + t] = lo;
            }
        }
        __syncthreads();

        // staging free -> prefetch next chunk (runs in background)
        if (n + 1 < NCHUNK)
            prefetch_chunk(sm, n + 1, b, h, split, tid, gq, gk, gv, gg, gb);

        // ---- P1: Grams  G=K@K^T and QK=Qg@K^T  (16x32 warp tiles, 4x2) ----
        {
            const int m0 = (warp >> 1) * 16, n0 = (warp & 1) * 32;
            float accG[4][4], accQ[4][4];
#pragma unroll
            for (int t = 0; t < 4; ++t)
#pragma unroll
                for (int e = 0; e < 4; ++e) { accG[t][e] = 0.f; accQ[t][e] = 0.f; }
            if (m0 + 15 >= n0) {   // skip fully-upper tiles (epilogue writes zeros)
                for (int k0 = 0; k0 < DK; k0 += 16) {
                    unsigned kh[4], kl[4], qh[4], ql[4];
                    ldA(sm.khi, KHS, m0, k0, gq_, tig, kh);
                    ldA(sm.klo, KHS, m0, k0, gq_, tig, kl);
                    ldA(sm.qhi, KHS, m0, k0, gq_, tig, qh);
                    ldA(sm.qlo, KHS, m0, k0, gq_, tig, ql);
#pragma unroll
                    for (int nt = 0; nt < 4; ++nt) {
                        unsigned bhh[2], bll[2];
                        ldB(sm.khi, KHS, n0 + nt * 8, k0, gq_, tig, bhh);
                        ldB(sm.klo, KHS, n0 + nt * 8, k0, gq_, tig, bll);
                        mma16816(accG[nt], kh[0], kh[1], kh[2], kh[3], bhh[0], bhh[1]);
                        mma16816(accG[nt], kh[0], kh[1], kh[2], kh[3], bll[0], bll[1]);
                        mma16816(accG[nt], kl[0], kl[1], kl[2], kl[3], bhh[0], bhh[1]);
                        mma16816(accQ[nt], qh[0], qh[1], qh[2], qh[3], bhh[0], bhh[1]);
                        mma16816(accQ[nt], qh[0], qh[1], qh[2], qh[3], bll[0], bll[1]);
                        mma16816(accQ[nt], ql[0], ql[1], ql[2], ql[3], bhh[0], bhh[1]);
                    }
                }
            }
            float einv = sm.iegc[CC - 1];   // e^{-g_last}
#pragma unroll
            for (int nt = 0; nt < 4; ++nt)
#pragma unroll
                for (int e = 0; e < 4; ++e) {
                    int i = m0 + gq_ + ((e >> 1) << 3);
                    int j = n0 + nt * 8 + 2 * tig + (e & 1);
                    float Av = (i > j) ? sm.negbe[i] * sm.iegc[j] * accG[nt][e] : 0.f;
                    sm.A[i * AS + j] = Av;
                    float atv = (i >= j) ? accQ[nt][e] * einv : 0.f;
                    __nv_bfloat16 hi, lo; bsplit(atv, hi, lo);
                    sm.athi[i * ATS + j] = hi;
                    sm.atlo[i * ATS + j] = lo;
                }
        }

        // ---- P2: rhs -= kw * (State^T @ K^T)^T  (16x16 tiles, 2x4) ----
        {
            const int m0 = (warp & 1) * 16, n0 = (warp >> 1) * 16;
            float acc[2][4];
#pragma unroll
            for (int t = 0; t < 2; ++t)
#pragma unroll
                for (int e = 0; e < 4; ++e) acc[t][e] = 0.f;
            for (int k0 = 0; k0 < DK; k0 += 16) {
                unsigned ah[4], al[4];
                ldA(sm.shi, KHS, m0, k0, gq_, tig, ah);
                ldA(sm.slo, KHS, m0, k0, gq_, tig, al);
#pragma unroll
                for (int nt = 0; nt < 2; ++nt) {
                    unsigned bhh[2], bll[2];
                    ldB(sm.khi, KHS, n0 + nt * 8, k0, gq_, tig, bhh);
                    ldB(sm.klo, KHS, n0 + nt * 8, k0, gq_, tig, bll);
                    mma16816(acc[nt], ah[0], ah[1], ah[2], ah[3], bhh[0], bhh[1]);
                    mma16816(acc[nt], ah[0], ah[1], ah[2], ah[3], bll[0], bll[1]);
                    mma16816(acc[nt], al[0], al[1], al[2], al[3], bhh[0], bhh[1]);
                }
            }
#pragma unroll
            for (int nt = 0; nt < 2; ++nt)
#pragma unroll
                for (int e = 0; e < 4; ++e) {
                    int i = m0 + gq_ + ((e >> 1) << 3);             // dv
                    int j = n0 + nt * 8 + 2 * tig + (e & 1);        // c
                    sm.v[j * VS + i] -= sm.kw[j] * acc[nt][e];
                }
        }
        __syncthreads();

        // ---- S1: invert the four 16x16 diagonal blocks (warps 0-3 parallel) ----
        if (warp < 4 && lane < 16) {
            const int r0 = warp * 16;
            float x[16];
#pragma unroll
            for (int r = 0; r < 16; ++r) {
                float acc = (r == lane) ? 1.f : 0.f;
#pragma unroll
                for (int j = 0; j < 16; ++j)
                    if (j < r) acc += sm.A[(r0 + r) * AS + r0 + j] * x[j];
                x[r] = acc;
                sm.Ti[warp * 272 + r * 17 + lane] = acc;
            }
        }
        if (warp == 0) {   // apply block 0 (warp 0 owns Ti[0]; per-lane column -> no race)
            __syncwarp();
            int c = lane;
            float x[16];
#pragma unroll
            for (int r = 0; r < 16; ++r) {
                float acc = 0.f;
#pragma unroll
                for (int j = 0; j <= r; ++j)
                    acc += sm.Ti[r * 17 + j] * sm.v[j * VS + c];
                x[r] = acc;
            }
#pragma unroll
            for (int r = 0; r < 16; ++r) sm.v[r * VS + c] = x[r];
        }
        __syncthreads();

        // ---- S2: remaining blocks: update rhs (all threads) + apply (1 warp) ----
#pragma unroll
        for (int blk = 1; blk < 4; ++blk) {
            {
                int row = blk * 16 + (tid >> 4);
                int c0 = (tid & 15) * 2;
                float a0 = 0.f, a1 = 0.f;
                for (int j = 0; j < blk * 16; ++j) {
                    float av = sm.A[row * AS + j];
                    a0 += av * sm.v[j * VS + c0];
                    a1 += av * sm.v[j * VS + c0 + 1];
                }
                sm.v[row * VS + c0] += a0;
                sm.v[row * VS + c0 + 1] += a1;
            }
            __syncthreads();
            if (warp == blk) {
                int c = lane;
                float x[16];
#pragma unroll
                for (int r = 0; r < 16; ++r) {
                    float acc = 0.f;
#pragma unroll
                    for (int j = 0; j <= r; ++j)
                        acc += sm.Ti[blk * 272 + r * 17 + j] *
                               sm.v[(blk * 16 + j) * VS + c];
                    x[r] = acc;
                }
#pragma unroll
                for (int r = 0; r < 16; ++r) sm.v[(blk * 16 + r) * VS + c] = x[r];
            }
            __syncthreads();
        }

        // ---- split (v_new * kdec)^T into bf16 hi/lo ----
        for (int idx = tid; idx < CC * DVS; idx += NT) {
            int c = idx >> 5, m = idx & 31;
            float x = sm.v[c * VS + m] * sm.kdec[c];
            __nv_bfloat16 hi, lo; bsplit(x, hi, lo);
            sm.vthi[m * VTS + c] = hi;
            sm.vtlo[m * VTS + c] = lo;
        }
        __syncthreads();

        // ---- P4: out^T = State^T@Qg^T + Vnewd^T@attn'^T  (16x16 tiles, 2x4) ----
        {
            const int m0 = (warp & 1) * 16, n0 = (warp >> 1) * 16;
            float acc[2][4];
#pragma unroll
            for (int t = 0; t < 2; ++t)
#pragma unroll
                for (int e = 0; e < 4; ++e) acc[t][e] = 0.f;
            for (int k0 = 0; k0 < DK; k0 += 16) {
                unsigned ah[4], al[4];
                ldA(sm.shi, KHS, m0, k0, gq_, tig, ah);
                ldA(sm.slo, KHS, m0, k0, gq_, tig, al);
#pragma unroll
                for (int nt = 0; nt < 2; ++nt) {
                    unsigned bhh[2], bll[2];
                    ldB(sm.qhi, KHS, n0 + nt * 8, k0, gq_, tig, bhh);
                    ldB(sm.qlo, KHS, n0 + nt * 8, k0, gq_, tig, bll);
                    mma16816(acc[nt], ah[0], ah[1], ah[2], ah[3], bhh[0], bhh[1]);
                    mma16816(acc[nt], ah[0], ah[1], ah[2], ah[3], bll[0], bll[1]);
                    mma16816(acc[nt], al[0], al[1], al[2], al[3], bhh[0], bhh[1]);
                }
            }
            for (int k0 = 0; k0 < CC; k0 += 16) {
                unsigned ah[4], al[4];
                ldA(sm.vthi, VTS, m0, k0, gq_, tig, ah);
                ldA(sm.vtlo, VTS, m0, k0, gq_, tig, al);
#pragma unroll
                for (int nt = 0; nt < 2; ++nt) {
                    unsigned bhh[2], bll[2];
                    ldB(sm.athi, ATS, n0 + nt * 8, k0, gq_, tig, bhh);
                    ldB(sm.atlo, ATS, n0 + nt * 8, k0, gq_, tig, bll);
                    mma16816(acc[nt], ah[0], ah[1], ah[2], ah[3], bhh[0], bhh[1]);
                    mma16816(acc[nt], ah[0], ah[1], ah[2], ah[3], bll[0], bll[1]);
                    mma16816(acc[nt], al[0], al[1], al[2], al[3], bhh[0], bhh[1]);
                }
            }
#pragma unroll
            for (int nt = 0; nt < 2; ++nt)
#pragma unroll
                for (int e = 0; e < 4; ++e) {
                    int dv = m0 + gq_ + ((e >> 1) << 3);
                    int c = n0 + nt * 8 + 2 * tig + (e & 1);
                    size_t ob = (((size_t)b * S_LEN + s0 + c) * NH + h) * (size_t)DV +
                                split * DVS + dv;
                    gout[ob] = acc[nt][e];
                }
        }

        // ---- P5 (MMA part): acc = Vnewd^T @ K  (16x32 tiles, 2x4) ----
        {
            const int m0 = (warp & 1) * 16, n0 = (warp >> 1) * 32;
            float acc[4][4];
#pragma unroll
            for (int t = 0; t < 4; ++t)
#pragma unroll
                for (int e = 0; e < 4; ++e) acc[t][e] = 0.f;
            for (int k0 = 0; k0 < CC; k0 += 16) {
                unsigned ah[4], al[4];
                ldA(sm.vthi, VTS, m0, k0, gq_, tig, ah);
                ldA(sm.vtlo, VTS, m0, k0, gq_, tig, al);
#pragma unroll
                for (int nt = 0; nt < 4; ++nt) {
                    int nn = n0 + nt * 8 + gq_;
                    unsigned bhh[2], bll[2];
                    ldBtrans(sm.khi, KHS, nn, k0, tig, bhh);
                    ldBtrans(sm.klo, KHS, nn, k0, tig, bll);
                    mma16816(acc[nt], ah[0], ah[1], ah[2], ah[3], bhh[0], bhh[1]);
                    mma16816(acc[nt], ah[0], ah[1], ah[2], ah[3], bll[0], bll[1]);
                    mma16816(acc[nt], al[0], al[1], al[2], al[3], bhh[0], bhh[1]);
                }
            }
            __syncthreads();   // all P4 reads of state done before RMW below
            float egl = sm.egc[CC - 1];
#pragma unroll
            for (int nt = 0; nt < 4; ++nt)
#pragma unroll
                for (int e = 0; e < 4; ++e) {
                    int dv = m0 + gq_ + ((e >> 1) << 3);
                    int dk = n0 + nt * 8 + 2 * tig + (e & 1);
                    float s_old = __bfloat162float(sm.shi[dv * KHS + dk]) +
                                  __bfloat162float(sm.slo[dv * KHS + dk]);
                    float s = s_old * egl + acc[nt][e];
                    __nv_bfloat16 hi, lo; bsplit(s, hi, lo);
                    sm.shi[dv * KHS + dk] = hi;
                    sm.slo[dv * KHS + dk] = lo;
                }
        }
    }
}

extern "C" void kernel_launch(void* const* d_in, const int* in_sizes, int n_in,
                              void* d_out, int out_size) {
    const float* q = (const float*)d_in[0];
    const float* k = (const float*)d_in[1];
    const float* v = (const float*)d_in[2];
    const float* g = (const float*)d_in[3];
    const float* beta = (const float*)d_in[4];
    float* out = (float*)d_out;

    int B = in_sizes[0] / (S_LEN * NH * DK);
    if (B < 1) B = 1;

    cudaFuncSetAttribute(gdn_kernel, cudaFuncAttributeMaxDynamicSharedMemorySize,
                         (int)sizeof(SmemT));
    gdn_kernel<<<B * NH * SPLIT, NT, sizeof(SmemT)>>>(q, k, v, g, beta, out);
}